// round 13
// baseline (speedup 1.0000x reference)
#include <cuda_runtime.h>
#include <math.h>

#define D      2048
#define NS     8
#define BSZ    16384
#define TWOD   (2*D)
#define PART_BLOCKS 256

// output layout: read [B,D] | attn [B,8] | alpha [1] | new_state [8,D] | new_fast [8,D]
#define OFF_READ   0
#define OFF_ATTN   ((size_t)BSZ * D)
#define OFF_ALPHA  (OFF_ATTN + (size_t)BSZ * NS)
#define OFF_NS     (OFF_ALPHA + 1)
#define OFF_NF     (OFF_NS + (size_t)NS * D)

#define FMA2(acc, a, b) \
    asm("fma.rn.f32x2 %0, %1, %2, %0;" : "+l"(acc) : "l"(a), "l"(b))
#define UNPK(lo, hi, v) \
    asm("mov.b64 {%0, %1}, %2;" : "=f"(lo), "=f"(hi) : "l"(v))
#define PREFETCH_L2(p) \
    asm volatile("prefetch.global.L2 [%0];" :: "l"(p))

// ---------------- device scratch (static, no allocs) ----------------
__device__ float g_S[NS * D];        // state + fast
__device__ float g_Keq[NS * D];      // keys @ Wr
__device__ float g_cq[NS];           // keys @ br
__device__ float g_sWc[NS];          // S @ Wc[0, D:2D]
__device__ float g_M1[NS * D];       // attn.T @ (h + nm)
__device__ float g_G[NS * NS];       // attn.T @ attn
__device__ float g_asum[NS];         // sum_b attn
__device__ float g_sadd;             // sum_b sigmoid(ctrl0)
__device__ float g_delta[NS * D];    // partial delta

// ---------------- prep1: S = state + fast ; zero accumulators ----------------
__global__ void k_prep1(const float* __restrict__ state, const float* __restrict__ fast) {
    int i = blockIdx.x * blockDim.x + threadIdx.x;   // 0..16383
    g_S[i]     = state[i] + fast[i];
    g_Keq[i]   = 0.f;
    g_M1[i]    = 0.f;
    g_delta[i] = 0.f;
    if (i < NS * NS) g_G[i] = 0.f;
    if (i < NS)      g_asum[i] = 0.f;
    if (i == 0)      g_sadd = 0.f;
}

// ---------------- keq: Keq[s,i] = sum_j keys[s,j] * Wr[j,i] ----------------
__global__ void k_keq(const float* __restrict__ keys, const float* __restrict__ Wr) {
    __shared__ float ks[NS][128];
    int t = threadIdx.x;
    int j0 = blockIdx.y * 128;
    int i  = blockIdx.x * 256 + t;
    for (int idx = t; idx < NS * 128; idx += 256)
        ks[idx >> 7][idx & 127] = keys[(idx >> 7) * D + j0 + (idx & 127)];
    __syncthreads();
    float acc[NS];
#pragma unroll
    for (int s = 0; s < NS; s++) acc[s] = 0.f;
    for (int jj = 0; jj < 128; jj++) {
        float w = Wr[(size_t)(j0 + jj) * D + i];
#pragma unroll
        for (int s = 0; s < NS; s++) acc[s] += ks[s][jj] * w;
    }
#pragma unroll
    for (int s = 0; s < NS; s++) atomicAdd(&g_Keq[s * D + i], acc[s]);
}

// ---------------- prep2: cq[s] = keys[s].br ; sWc[s] = S[s].Wc[0,D:] ----------------
__global__ void k_prep2(const float* __restrict__ keys, const float* __restrict__ br,
                        const float* __restrict__ Wc) {
    __shared__ float rbuf[8];
    int s = blockIdx.x >> 1;
    int which = blockIdx.x & 1;
    const float* a = which ? (g_S + s * D) : (keys + s * D);
    const float* w = which ? (Wc + D) : br;
    float acc = 0.f;
    for (int i = threadIdx.x; i < D; i += 256) acc += a[i] * w[i];
#pragma unroll
    for (int off = 16; off; off >>= 1) acc += __shfl_xor_sync(0xffffffffu, acc, off);
    if ((threadIdx.x & 31) == 0) rbuf[threadIdx.x >> 5] = acc;
    __syncthreads();
    if (threadIdx.x == 0) {
        float tot = 0.f;
#pragma unroll
        for (int k = 0; k < 8; k++) tot += rbuf[k];
        if (which) g_sWc[s] = tot; else g_cq[s] = tot;
    }
}

// ---------------- P1: 4 rows/warp, 8 lanes/row, MLP-8, next-quad L2 prefetch -
__global__ __launch_bounds__(256)
void k_part(const float* __restrict__ h, const float* __restrict__ Wc,
            const float* __restrict__ bc, float* __restrict__ attn_out) {
    extern __shared__ float kq_sm[];    // [9][2048]
    __shared__ float cq_sm[8], swc_sm[8];
    int t = threadIdx.x;
    for (int i = t; i < (NS * D) / 4; i += 256)
        ((float4*)kq_sm)[i] = ((const float4*)g_Keq)[i];
    for (int i = t; i < D / 4; i += 256)
        ((float4*)(kq_sm + NS * D))[i] = ((const float4*)Wc)[i];
    if (t < 8) { cq_sm[t] = g_cq[t]; swc_sm[t] = g_sWc[t]; }
    float bc0 = bc[0];
    __syncthreads();

    int lane = t & 31;
    int sub  = lane >> 3;       // row within quad (0..3)
    int cid  = lane & 7;        // column chunk (0..7)
    int gw = blockIdx.x * 8 + (t >> 5);
    int nw = PART_BLOCKS * 8;   // 2048 warp-groups, 2 quads each
    float saddl = 0.f;
    const char* kbase = (const char*)kq_sm + cid * 16;

    for (int q = gw; q < BSZ / 4; q += nw) {
        int row = q * 4 + sub;
        const char* hrow = (const char*)(h + (size_t)row * D);
        // prefetch NEXT quad's row into L2 — a full quad of compute (~us)
        // separates this prefetch from its demand loads
        int qn = q + nw;
        if (qn < BSZ / 4) {
            const char* hnext = (const char*)(h + (size_t)(qn * 4 + sub) * D);
#pragma unroll
            for (int p = 0; p < 8; p++)
                PREFETCH_L2(hnext + (size_t)(cid + 8 * p) * 128);
        }
        const char* hp = hrow + cid * 16;
        unsigned long long acc[9];
#pragma unroll
        for (int v = 0; v < 9; v++) acc[v] = 0ull;
#pragma unroll 1
        for (int blk = 0; blk < 64; blk += 8) {
            // 8 independent LDG.128 issued back-to-back (MLP 8)
            const char* hb = hp + (size_t)blk * 128;
            ulonglong2 hv0 = *(const ulonglong2*)(hb);
            ulonglong2 hv1 = *(const ulonglong2*)(hb + 128);
            ulonglong2 hv2 = *(const ulonglong2*)(hb + 256);
            ulonglong2 hv3 = *(const ulonglong2*)(hb + 384);
            ulonglong2 hv4 = *(const ulonglong2*)(hb + 512);
            ulonglong2 hv5 = *(const ulonglong2*)(hb + 640);
            ulonglong2 hv6 = *(const ulonglong2*)(hb + 768);
            ulonglong2 hv7 = *(const ulonglong2*)(hb + 896);
            const char* kb = kbase + blk * 128;
#pragma unroll
            for (int v = 0; v < 9; v++) {
                const char* kv = kb + v * (D * 4);
                ulonglong2 k0 = *(const ulonglong2*)(kv);
                FMA2(acc[v], hv0.x, k0.x); FMA2(acc[v], hv0.y, k0.y);
                ulonglong2 k1 = *(const ulonglong2*)(kv + 128);
                FMA2(acc[v], hv1.x, k1.x); FMA2(acc[v], hv1.y, k1.y);
                ulonglong2 k2 = *(const ulonglong2*)(kv + 256);
                FMA2(acc[v], hv2.x, k2.x); FMA2(acc[v], hv2.y, k2.y);
                ulonglong2 k3 = *(const ulonglong2*)(kv + 384);
                FMA2(acc[v], hv3.x, k3.x); FMA2(acc[v], hv3.y, k3.y);
                ulonglong2 k4 = *(const ulonglong2*)(kv + 512);
                FMA2(acc[v], hv4.x, k4.x); FMA2(acc[v], hv4.y, k4.y);
                ulonglong2 k5 = *(const ulonglong2*)(kv + 640);
                FMA2(acc[v], hv5.x, k5.x); FMA2(acc[v], hv5.y, k5.y);
                ulonglong2 k6 = *(const ulonglong2*)(kv + 768);
                FMA2(acc[v], hv6.x, k6.x); FMA2(acc[v], hv6.y, k6.y);
                ulonglong2 k7 = *(const ulonglong2*)(kv + 896);
                FMA2(acc[v], hv7.x, k7.x); FMA2(acc[v], hv7.y, k7.y);
            }
        }
        float r[9];
#pragma unroll
        for (int v = 0; v < 9; v++) {
            float lo, hi;
            UNPK(lo, hi, acc[v]);
            r[v] = lo + hi;
        }
        // butterfly over the 8 lanes of this row group
#pragma unroll
        for (int d = 1; d < 8; d <<= 1) {
#pragma unroll
            for (int v = 0; v < 9; v++)
                r[v] += __shfl_xor_sync(0xffffffffu, r[v], d);
        }
        // softmax (redundant across the 8 lanes)
        float lg[8], m = -1e30f;
#pragma unroll
        for (int v = 0; v < 8; v++) { lg[v] = r[v] + cq_sm[v]; m = fmaxf(m, lg[v]); }
        float se = 0.f;
#pragma unroll
        for (int v = 0; v < 8; v++) { lg[v] = expf(lg[v] - m); se += lg[v]; }
        float inv = 1.f / se;
        float aw = 0.f;
#pragma unroll
        for (int v = 0; v < 8; v++) { lg[v] *= inv; aw += lg[v] * swc_sm[v]; }
        if (cid == 0) {
            float4 o0 = {lg[0], lg[1], lg[2], lg[3]};
            float4 o1 = {lg[4], lg[5], lg[6], lg[7]};
            *(float4*)(attn_out + (size_t)row * NS)     = o0;
            *(float4*)(attn_out + (size_t)row * NS + 4) = o1;
            saddl += 1.f / (1.f + expf(-(r[8] + aw + bc0)));
        }
    }
    // sum saddl from lanes 0,8,16,24 (others hold 0)
    saddl += __shfl_xor_sync(0xffffffffu, saddl, 8);
    saddl += __shfl_xor_sync(0xffffffffu, saddl, 16);
    if (lane == 0) atomicAdd(&g_sadd, saddl);
}

// ---------------- P2: streaming, column-split, reg prefetch + L2 prefetch ----
#define SSTEP(s, as) { \
    float4 sv = s_sm[(s) * 256 + t]; \
    m1[s][0] += (as) * hn0; m1[s][1] += (as) * hn1; \
    m1[s][2] += (as) * hn2; m1[s][3] += (as) * hn3; \
    rd.x += (as) * sv.x; rd.y += (as) * sv.y; \
    rd.z += (as) * sv.z; rd.w += (as) * sv.w; }

__global__ __launch_bounds__(256)
void k_stream(const float* __restrict__ h, const float* __restrict__ nm,
              const float* __restrict__ attn, float* __restrict__ read_out) {
    extern __shared__ float4 s_sm[];   // [NS][256]: one 1024-col half of S
    int t = threadIdx.x;
    int half = blockIdx.x & 1;
    int colbase = half * (D / 2);
#pragma unroll
    for (int s = 0; s < NS; s++)
        s_sm[s * 256 + t] = ((const float4*)(g_S + s * D + colbase))[t];
    float m1[NS][4];
#pragma unroll
    for (int s = 0; s < NS; s++) { m1[s][0]=0.f; m1[s][1]=0.f; m1[s][2]=0.f; m1[s][3]=0.f; }
    float gl = 0.f, asl = 0.f;
    int gi = (t >> 3) & 7, gj = t & 7;
    __syncthreads();

    int bstride = gridDim.x >> 1;
    int b0 = blockIdx.x >> 1;
    float4 hv = ((const float4*)(h  + (size_t)b0 * D + colbase))[t];
    float4 nv = ((const float4*)(nm + (size_t)b0 * D + colbase))[t];
    float4 a0 = ((const float4*)(attn + (size_t)b0 * NS))[0];
    float4 a1 = ((const float4*)(attn + (size_t)b0 * NS))[1];

    for (int b = b0; b < BSZ; b += bstride) {
        float4 hc = hv, nc = nv, ac0 = a0, ac1 = a1;
        int bn = b + bstride;
        if (bn < BSZ) {   // register prefetch (1 row ahead)
            hv = ((const float4*)(h  + (size_t)bn * D + colbase))[t];
            nv = ((const float4*)(nm + (size_t)bn * D + colbase))[t];
            a0 = ((const float4*)(attn + (size_t)bn * NS))[0];
            a1 = ((const float4*)(attn + (size_t)bn * NS))[1];
        }
        int b2 = b + 2 * bstride;
        if (b2 < BSZ) {   // L2 prefetch (2 rows ahead, zero reg cost)
            PREFETCH_L2((const char*)(h  + (size_t)b2 * D + colbase) + t * 16);
            PREFETCH_L2((const char*)(nm + (size_t)b2 * D + colbase) + t * 16);
        }
        float hn0 = hc.x + nc.x, hn1 = hc.y + nc.y;
        float hn2 = hc.z + nc.z, hn3 = hc.w + nc.w;
        float4 rd = {0.f,0.f,0.f,0.f};
        SSTEP(0, ac0.x) SSTEP(1, ac0.y) SSTEP(2, ac0.z) SSTEP(3, ac0.w)
        SSTEP(4, ac1.x) SSTEP(5, ac1.y) SSTEP(6, ac1.z) SSTEP(7, ac1.w)
        ((float4*)(read_out + (size_t)b * D + colbase))[t] = rd;
        if (half == 0) {    // G/asum once per row (L1-resident scalar loads)
            gl  += attn[(size_t)b * NS + gi] * attn[(size_t)b * NS + gj];
            asl += attn[(size_t)b * NS + gj];
        }
    }
#pragma unroll
    for (int s = 0; s < NS; s++) {
#pragma unroll
        for (int k = 0; k < 4; k++)
            atomicAdd(&g_M1[s * D + colbase + 4 * t + k], m1[s][k]);
    }
    if (half == 0 && t < 64) atomicAdd(&g_G[t], gl);
    if (half == 0 && t < 8)  atomicAdd(&g_asum[t], asl);
}

// ---------------- delta partials: [M1 | G@S] @ Ww^T ----------------
__global__ __launch_bounds__(256)
void k_delta(const float* __restrict__ Ww) {
    __shared__ float u_sm[NS][256];
    __shared__ float gsm[64];
    int t = threadIdx.x;
    int i0 = blockIdx.y * 256;                  // 0..4095
    int ui0 = i0 & (D - 1);
    if (i0 >= D && t < 64) gsm[t] = g_G[t];
    __syncthreads();
    if (i0 < D) {
        for (int idx = t; idx < NS * 256; idx += 256)
            u_sm[idx >> 8][idx & 255] = g_M1[(idx >> 8) * D + ui0 + (idx & 255)];
    } else {
        float sv[NS];
#pragma unroll
        for (int sp = 0; sp < NS; sp++) sv[sp] = g_S[sp * D + ui0 + t];
#pragma unroll
        for (int s = 0; s < NS; s++) {
            float u = 0.f;
#pragma unroll
            for (int sp = 0; sp < NS; sp++) u += gsm[s * NS + sp] * sv[sp];
            u_sm[s][t] = u;
        }
    }
    __syncthreads();
    int o = blockIdx.x * 256 + t;
    float acc[NS];
#pragma unroll
    for (int s = 0; s < NS; s++) acc[s] = 0.f;
    const float* wrow = Ww + (size_t)o * TWOD + i0;
    for (int ii = 0; ii < 256; ii += 4) {
        float4 w = *(const float4*)(wrow + ii);
#pragma unroll
        for (int s = 0; s < NS; s++)
            acc[s] += u_sm[s][ii]*w.x + u_sm[s][ii+1]*w.y + u_sm[s][ii+2]*w.z + u_sm[s][ii+3]*w.w;
    }
#pragma unroll
    for (int s = 0; s < NS; s++) atomicAdd(&g_delta[s * D + o], acc[s]);
}

// ---------------- final: alpha, new_state, new_fast ----------------
__global__ void k_final(const float* __restrict__ bw, const float* __restrict__ state,
                        const float* __restrict__ fast, float* __restrict__ out) {
    int idx = blockIdx.x * 256 + threadIdx.x;   // 16384
    float mean = g_sadd * (1.f / (float)BSZ);
    float alpha = 0.02f + 0.98f * mean;
    alpha = fminf(fmaxf(alpha, 0.f), 1.f);      // ALPHA_BOOST = 1
    int s = idx >> 11, o = idx & (D - 1);
    float delta = g_delta[idx] + g_asum[s] * bw[o];
    out[OFF_NS + idx] = (1.f - alpha) * state[idx] + alpha * delta;
    out[OFF_NF + idx] = 0.95f * fast[idx] + 0.05f * delta;
    if (idx == 0) out[OFF_ALPHA] = alpha;
}

// ---------------- launch ----------------
extern "C" void kernel_launch(void* const* d_in, const int* in_sizes, int n_in,
                              void* d_out, int out_size) {
    const float* h     = (const float*)d_in[0];
    const float* nm    = (const float*)d_in[1];
    const float* keys  = (const float*)d_in[2];
    const float* Wr    = (const float*)d_in[3];
    const float* br    = (const float*)d_in[4];
    const float* Wc    = (const float*)d_in[5];
    const float* bc    = (const float*)d_in[6];
    const float* Ww    = (const float*)d_in[7];
    const float* bw    = (const float*)d_in[8];
    const float* state = (const float*)d_in[9];
    const float* fast  = (const float*)d_in[10];
    float* out = (float*)d_out;

    const int SMEM_PART = 9 * D * sizeof(float);          // 72KB keq tile
    const int SMEM_STRM = NS * 256 * sizeof(float4);      // 32KB S half tile
    cudaFuncSetAttribute(k_part,   cudaFuncAttributeMaxDynamicSharedMemorySize, SMEM_PART);
    cudaFuncSetAttribute(k_stream, cudaFuncAttributeMaxDynamicSharedMemorySize, SMEM_STRM);

    k_prep1<<<64, 256>>>(state, fast);
    k_keq<<<dim3(8, 16), 256>>>(keys, Wr);
    k_prep2<<<16, 256>>>(keys, br, Wc);
    k_part<<<PART_BLOCKS, 256, SMEM_PART>>>(h, Wc, bc, out + OFF_ATTN);  // 2048 warps x 2 quads
    k_stream<<<888, 256, SMEM_STRM>>>(h, nm, out + OFF_ATTN, out + OFF_READ);
    k_delta<<<dim3(8, 16), 256>>>(Ww);
    k_final<<<64, 256>>>(bw, state, fast, out);
}

// round 14
// speedup vs baseline: 1.3179x; 1.3179x over previous
#include <cuda_runtime.h>
#include <math.h>

#define D      2048
#define NS     8
#define BSZ    16384
#define TWOD   (2*D)

// output layout: read [B,D] | attn [B,8] | alpha [1] | new_state [8,D] | new_fast [8,D]
#define OFF_READ   0
#define OFF_ATTN   ((size_t)BSZ * D)
#define OFF_ALPHA  (OFF_ATTN + (size_t)BSZ * NS)
#define OFF_NS     (OFF_ALPHA + 1)
#define OFF_NF     (OFF_NS + (size_t)NS * D)

#define FMA2(acc, a, b) \
    asm("fma.rn.f32x2 %0, %1, %2, %0;" : "+l"(acc) : "l"(a), "l"(b))
#define UNPK(lo, hi, v) \
    asm("mov.b64 {%0, %1}, %2;" : "=f"(lo), "=f"(hi) : "l"(v))
#define PREFETCH_L2(p) \
    asm volatile("prefetch.global.L2 [%0];" :: "l"(p))

// ---------------- device scratch (static, no allocs) ----------------
__device__ float g_S[NS * D];        // state + fast
__device__ float g_Keq[NS * D];      // keys @ Wr
__device__ float g_cq[NS];           // keys @ br
__device__ float g_sWc[NS];          // S @ Wc[0, D:2D]
__device__ float g_M1[NS * D];       // attn.T @ (h + nm)
__device__ float g_G[NS * NS];       // attn.T @ attn
__device__ float g_asum[NS];         // sum_b attn
__device__ float g_sadd;             // sum_b sigmoid(ctrl0)
__device__ float g_delta[NS * D];    // partial delta

// ---------------- prep1: S = state + fast ; zero accumulators ----------------
__global__ void k_prep1(const float* __restrict__ state, const float* __restrict__ fast) {
    int i = blockIdx.x * blockDim.x + threadIdx.x;   // 0..16383
    g_S[i]     = state[i] + fast[i];
    g_Keq[i]   = 0.f;
    g_M1[i]    = 0.f;
    g_delta[i] = 0.f;
    if (i < NS * NS) g_G[i] = 0.f;
    if (i < NS)      g_asum[i] = 0.f;
    if (i == 0)      g_sadd = 0.f;
}

// ---------------- keq: Keq[s,i] = sum_j keys[s,j] * Wr[j,i] ----------------
__global__ void k_keq(const float* __restrict__ keys, const float* __restrict__ Wr) {
    __shared__ float ks[NS][128];
    int t = threadIdx.x;
    int j0 = blockIdx.y * 128;
    int i  = blockIdx.x * 256 + t;
    for (int idx = t; idx < NS * 128; idx += 256)
        ks[idx >> 7][idx & 127] = keys[(idx >> 7) * D + j0 + (idx & 127)];
    __syncthreads();
    float acc[NS];
#pragma unroll
    for (int s = 0; s < NS; s++) acc[s] = 0.f;
    for (int jj = 0; jj < 128; jj++) {
        float w = Wr[(size_t)(j0 + jj) * D + i];
#pragma unroll
        for (int s = 0; s < NS; s++) acc[s] += ks[s][jj] * w;
    }
#pragma unroll
    for (int s = 0; s < NS; s++) atomicAdd(&g_Keq[s * D + i], acc[s]);
}

// ---------------- prep2: cq[s] = keys[s].br ; sWc[s] = S[s].Wc[0,D:] ----------------
__global__ void k_prep2(const float* __restrict__ keys, const float* __restrict__ br,
                        const float* __restrict__ Wc) {
    __shared__ float rbuf[8];
    int s = blockIdx.x >> 1;
    int which = blockIdx.x & 1;
    const float* a = which ? (g_S + s * D) : (keys + s * D);
    const float* w = which ? (Wc + D) : br;
    float acc = 0.f;
    for (int i = threadIdx.x; i < D; i += 256) acc += a[i] * w[i];
#pragma unroll
    for (int off = 16; off; off >>= 1) acc += __shfl_xor_sync(0xffffffffu, acc, off);
    if ((threadIdx.x & 31) == 0) rbuf[threadIdx.x >> 5] = acc;
    __syncthreads();
    if (threadIdx.x == 0) {
        float tot = 0.f;
#pragma unroll
        for (int k = 0; k < 8; k++) tot += rbuf[k];
        if (which) g_sWc[s] = tot; else g_cq[s] = tot;
    }
}

// ---------------- P1: 4 rows/warp, 8 lanes/row, MLP-8, intra-quad prefetch ---
__global__ __launch_bounds__(256)
void k_part(const float* __restrict__ h, const float* __restrict__ Wc,
            const float* __restrict__ bc, float* __restrict__ attn_out) {
    extern __shared__ float kq_sm[];    // [9][2048]
    __shared__ float cq_sm[8], swc_sm[8];
    int t = threadIdx.x;
    for (int i = t; i < (NS * D) / 4; i += 256)
        ((float4*)kq_sm)[i] = ((const float4*)g_Keq)[i];
    for (int i = t; i < D / 4; i += 256)
        ((float4*)(kq_sm + NS * D))[i] = ((const float4*)Wc)[i];
    if (t < 8) { cq_sm[t] = g_cq[t]; swc_sm[t] = g_sWc[t]; }
    float bc0 = bc[0];
    __syncthreads();

    int lane = t & 31;
    int sub  = lane >> 3;       // row within quad (0..3)
    int cid  = lane & 7;        // column chunk (0..7)
    int gw = blockIdx.x * 8 + (t >> 5);
    int nw = gridDim.x * 8;
    float saddl = 0.f;
    const char* kbase = (const char*)kq_sm + cid * 16;

    for (int q = gw; q < BSZ / 4; q += nw) {
        int row = q * 4 + sub;
        const char* hrow = (const char*)(h + (size_t)row * D);
        // intra-quad prefetch: lines 16..63 are demanded 2-8 blk-iterations
        // from now — overlap their DRAM latency with compute on lines 0..15.
        // lane cid covers lines {16+cid, 24+cid, ..., 56+cid} (8 lanes x 6 = 48)
#pragma unroll
        for (int p = 0; p < 6; p++)
            PREFETCH_L2(hrow + (size_t)(16 + cid + 8 * p) * 128);
        const char* hp = hrow + cid * 16;
        unsigned long long acc[9];
#pragma unroll
        for (int v = 0; v < 9; v++) acc[v] = 0ull;
#pragma unroll 1
        for (int blk = 0; blk < 64; blk += 8) {
            // 8 independent LDG.128 issued back-to-back (MLP 8)
            const char* hb = hp + (size_t)blk * 128;
            ulonglong2 hv0 = *(const ulonglong2*)(hb);
            ulonglong2 hv1 = *(const ulonglong2*)(hb + 128);
            ulonglong2 hv2 = *(const ulonglong2*)(hb + 256);
            ulonglong2 hv3 = *(const ulonglong2*)(hb + 384);
            ulonglong2 hv4 = *(const ulonglong2*)(hb + 512);
            ulonglong2 hv5 = *(const ulonglong2*)(hb + 640);
            ulonglong2 hv6 = *(const ulonglong2*)(hb + 768);
            ulonglong2 hv7 = *(const ulonglong2*)(hb + 896);
            const char* kb = kbase + blk * 128;
#pragma unroll
            for (int v = 0; v < 9; v++) {
                const char* kv = kb + v * (D * 4);
                ulonglong2 k0 = *(const ulonglong2*)(kv);
                FMA2(acc[v], hv0.x, k0.x); FMA2(acc[v], hv0.y, k0.y);
                ulonglong2 k1 = *(const ulonglong2*)(kv + 128);
                FMA2(acc[v], hv1.x, k1.x); FMA2(acc[v], hv1.y, k1.y);
                ulonglong2 k2 = *(const ulonglong2*)(kv + 256);
                FMA2(acc[v], hv2.x, k2.x); FMA2(acc[v], hv2.y, k2.y);
                ulonglong2 k3 = *(const ulonglong2*)(kv + 384);
                FMA2(acc[v], hv3.x, k3.x); FMA2(acc[v], hv3.y, k3.y);
                ulonglong2 k4 = *(const ulonglong2*)(kv + 512);
                FMA2(acc[v], hv4.x, k4.x); FMA2(acc[v], hv4.y, k4.y);
                ulonglong2 k5 = *(const ulonglong2*)(kv + 640);
                FMA2(acc[v], hv5.x, k5.x); FMA2(acc[v], hv5.y, k5.y);
                ulonglong2 k6 = *(const ulonglong2*)(kv + 768);
                FMA2(acc[v], hv6.x, k6.x); FMA2(acc[v], hv6.y, k6.y);
                ulonglong2 k7 = *(const ulonglong2*)(kv + 896);
                FMA2(acc[v], hv7.x, k7.x); FMA2(acc[v], hv7.y, k7.y);
            }
        }
        float r[9];
#pragma unroll
        for (int v = 0; v < 9; v++) {
            float lo, hi;
            UNPK(lo, hi, acc[v]);
            r[v] = lo + hi;
        }
        // butterfly over the 8 lanes of this row group
#pragma unroll
        for (int d = 1; d < 8; d <<= 1) {
#pragma unroll
            for (int v = 0; v < 9; v++)
                r[v] += __shfl_xor_sync(0xffffffffu, r[v], d);
        }
        // softmax (redundant across the 8 lanes)
        float lg[8], m = -1e30f;
#pragma unroll
        for (int v = 0; v < 8; v++) { lg[v] = r[v] + cq_sm[v]; m = fmaxf(m, lg[v]); }
        float se = 0.f;
#pragma unroll
        for (int v = 0; v < 8; v++) { lg[v] = expf(lg[v] - m); se += lg[v]; }
        float inv = 1.f / se;
        float aw = 0.f;
#pragma unroll
        for (int v = 0; v < 8; v++) { lg[v] *= inv; aw += lg[v] * swc_sm[v]; }
        if (cid == 0) {
            float4 o0 = {lg[0], lg[1], lg[2], lg[3]};
            float4 o1 = {lg[4], lg[5], lg[6], lg[7]};
            *(float4*)(attn_out + (size_t)row * NS)     = o0;
            *(float4*)(attn_out + (size_t)row * NS + 4) = o1;
            saddl += 1.f / (1.f + expf(-(r[8] + aw + bc0)));
        }
    }
    // sum saddl from lanes 0,8,16,24 (others hold 0)
    saddl += __shfl_xor_sync(0xffffffffu, saddl, 8);
    saddl += __shfl_xor_sync(0xffffffffu, saddl, 16);
    if (lane == 0) atomicAdd(&g_sadd, saddl);
}

// ---------------- P2: streaming, column-split, reg prefetch + L2 prefetch ----
#define SSTEP(s, as) { \
    float4 sv = s_sm[(s) * 256 + t]; \
    m1[s][0] += (as) * hn0; m1[s][1] += (as) * hn1; \
    m1[s][2] += (as) * hn2; m1[s][3] += (as) * hn3; \
    rd.x += (as) * sv.x; rd.y += (as) * sv.y; \
    rd.z += (as) * sv.z; rd.w += (as) * sv.w; }

__global__ __launch_bounds__(256)
void k_stream(const float* __restrict__ h, const float* __restrict__ nm,
              const float* __restrict__ attn, float* __restrict__ read_out) {
    extern __shared__ float4 s_sm[];   // [NS][256]: one 1024-col half of S
    int t = threadIdx.x;
    int half = blockIdx.x & 1;
    int colbase = half * (D / 2);
#pragma unroll
    for (int s = 0; s < NS; s++)
        s_sm[s * 256 + t] = ((const float4*)(g_S + s * D + colbase))[t];
    float m1[NS][4];
#pragma unroll
    for (int s = 0; s < NS; s++) { m1[s][0]=0.f; m1[s][1]=0.f; m1[s][2]=0.f; m1[s][3]=0.f; }
    float gl = 0.f, asl = 0.f;
    int gi = (t >> 3) & 7, gj = t & 7;
    __syncthreads();

    int bstride = gridDim.x >> 1;
    int b0 = blockIdx.x >> 1;
    float4 hv = ((const float4*)(h  + (size_t)b0 * D + colbase))[t];
    float4 nv = ((const float4*)(nm + (size_t)b0 * D + colbase))[t];
    float4 a0 = ((const float4*)(attn + (size_t)b0 * NS))[0];
    float4 a1 = ((const float4*)(attn + (size_t)b0 * NS))[1];

    for (int b = b0; b < BSZ; b += bstride) {
        float4 hc = hv, nc = nv, ac0 = a0, ac1 = a1;
        int bn = b + bstride;
        if (bn < BSZ) {   // register prefetch (1 row ahead)
            hv = ((const float4*)(h  + (size_t)bn * D + colbase))[t];
            nv = ((const float4*)(nm + (size_t)bn * D + colbase))[t];
            a0 = ((const float4*)(attn + (size_t)bn * NS))[0];
            a1 = ((const float4*)(attn + (size_t)bn * NS))[1];
        }
        int b2 = b + 3 * bstride;
        if (b2 < BSZ) {   // L2 prefetch (3 rows ahead, zero reg cost)
            PREFETCH_L2((const char*)(h  + (size_t)b2 * D + colbase) + t * 16);
            PREFETCH_L2((const char*)(nm + (size_t)b2 * D + colbase) + t * 16);
        }
        float hn0 = hc.x + nc.x, hn1 = hc.y + nc.y;
        float hn2 = hc.z + nc.z, hn3 = hc.w + nc.w;
        float4 rd = {0.f,0.f,0.f,0.f};
        SSTEP(0, ac0.x) SSTEP(1, ac0.y) SSTEP(2, ac0.z) SSTEP(3, ac0.w)
        SSTEP(4, ac1.x) SSTEP(5, ac1.y) SSTEP(6, ac1.z) SSTEP(7, ac1.w)
        ((float4*)(read_out + (size_t)b * D + colbase))[t] = rd;
        if (half == 0) {    // G/asum once per row (L1-resident scalar loads)
            gl  += attn[(size_t)b * NS + gi] * attn[(size_t)b * NS + gj];
            asl += attn[(size_t)b * NS + gj];
        }
    }
#pragma unroll
    for (int s = 0; s < NS; s++) {
#pragma unroll
        for (int k = 0; k < 4; k++)
            atomicAdd(&g_M1[s * D + colbase + 4 * t + k], m1[s][k]);
    }
    if (half == 0 && t < 64) atomicAdd(&g_G[t], gl);
    if (half == 0 && t < 8)  atomicAdd(&g_asum[t], asl);
}

// ---------------- delta partials: [M1 | G@S] @ Ww^T ----------------
__global__ __launch_bounds__(256)
void k_delta(const float* __restrict__ Ww) {
    __shared__ float u_sm[NS][256];
    __shared__ float gsm[64];
    int t = threadIdx.x;
    int i0 = blockIdx.y * 256;                  // 0..4095
    int ui0 = i0 & (D - 1);
    if (i0 >= D && t < 64) gsm[t] = g_G[t];
    __syncthreads();
    if (i0 < D) {
        for (int idx = t; idx < NS * 256; idx += 256)
            u_sm[idx >> 8][idx & 255] = g_M1[(idx >> 8) * D + ui0 + (idx & 255)];
    } else {
        float sv[NS];
#pragma unroll
        for (int sp = 0; sp < NS; sp++) sv[sp] = g_S[sp * D + ui0 + t];
#pragma unroll
        for (int s = 0; s < NS; s++) {
            float u = 0.f;
#pragma unroll
            for (int sp = 0; sp < NS; sp++) u += gsm[s * NS + sp] * sv[sp];
            u_sm[s][t] = u;
        }
    }
    __syncthreads();
    int o = blockIdx.x * 256 + t;
    float acc[NS];
#pragma unroll
    for (int s = 0; s < NS; s++) acc[s] = 0.f;
    const float* wrow = Ww + (size_t)o * TWOD + i0;
    for (int ii = 0; ii < 256; ii += 4) {
        float4 w = *(const float4*)(wrow + ii);
#pragma unroll
        for (int s = 0; s < NS; s++)
            acc[s] += u_sm[s][ii]*w.x + u_sm[s][ii+1]*w.y + u_sm[s][ii+2]*w.z + u_sm[s][ii+3]*w.w;
    }
#pragma unroll
    for (int s = 0; s < NS; s++) atomicAdd(&g_delta[s * D + o], acc[s]);
}

// ---------------- final: alpha, new_state, new_fast ----------------
__global__ void k_final(const float* __restrict__ bw, const float* __restrict__ state,
                        const float* __restrict__ fast, float* __restrict__ out) {
    int idx = blockIdx.x * 256 + threadIdx.x;   // 16384
    float mean = g_sadd * (1.f / (float)BSZ);
    float alpha = 0.02f + 0.98f * mean;
    alpha = fminf(fmaxf(alpha, 0.f), 1.f);      // ALPHA_BOOST = 1
    int s = idx >> 11, o = idx & (D - 1);
    float delta = g_delta[idx] + g_asum[s] * bw[o];
    out[OFF_NS + idx] = (1.f - alpha) * state[idx] + alpha * delta;
    out[OFF_NF + idx] = 0.95f * fast[idx] + 0.05f * delta;
    if (idx == 0) out[OFF_ALPHA] = alpha;
}

// ---------------- launch ----------------
extern "C" void kernel_launch(void* const* d_in, const int* in_sizes, int n_in,
                              void* d_out, int out_size) {
    const float* h     = (const float*)d_in[0];
    const float* nm    = (const float*)d_in[1];
    const float* keys  = (const float*)d_in[2];
    const float* Wr    = (const float*)d_in[3];
    const float* br    = (const float*)d_in[4];
    const float* Wc    = (const float*)d_in[5];
    const float* bc    = (const float*)d_in[6];
    const float* Ww    = (const float*)d_in[7];
    const float* bw    = (const float*)d_in[8];
    const float* state = (const float*)d_in[9];
    const float* fast  = (const float*)d_in[10];
    float* out = (float*)d_out;

    const int SMEM_PART = 9 * D * sizeof(float);          // 72KB keq tile
    const int SMEM_STRM = NS * 256 * sizeof(float4);      // 32KB S half tile
    cudaFuncSetAttribute(k_part,   cudaFuncAttributeMaxDynamicSharedMemorySize, SMEM_PART);
    cudaFuncSetAttribute(k_stream, cudaFuncAttributeMaxDynamicSharedMemorySize, SMEM_STRM);

    k_prep1<<<64, 256>>>(state, fast);
    k_keq<<<dim3(8, 16), 256>>>(keys, Wr);
    k_prep2<<<16, 256>>>(keys, br, Wc);
    k_part<<<512, 256, SMEM_PART>>>(h, Wc, bc, out + OFF_ATTN);   // 4096 warps x 1 quad
    k_stream<<<888, 256, SMEM_STRM>>>(h, nm, out + OFF_ATTN, out + OFF_READ);
    k_delta<<<dim3(8, 16), 256>>>(Ww);
    k_final<<<64, 256>>>(bw, state, fast, out);
}

// round 15
// speedup vs baseline: 1.3290x; 1.0084x over previous
#include <cuda_runtime.h>
#include <math.h>

#define D      2048
#define NS     8
#define BSZ    16384
#define TWOD   (2*D)

// output layout: read [B,D] | attn [B,8] | alpha [1] | new_state [8,D] | new_fast [8,D]
#define OFF_READ   0
#define OFF_ATTN   ((size_t)BSZ * D)
#define OFF_ALPHA  (OFF_ATTN + (size_t)BSZ * NS)
#define OFF_NS     (OFF_ALPHA + 1)
#define OFF_NF     (OFF_NS + (size_t)NS * D)

#define FMA2(acc, a, b) \
    asm("fma.rn.f32x2 %0, %1, %2, %0;" : "+l"(acc) : "l"(a), "l"(b))
#define UNPK(lo, hi, v) \
    asm("mov.b64 {%0, %1}, %2;" : "=f"(lo), "=f"(hi) : "l"(v))
#define PREFETCH_L2(p) \
    asm volatile("prefetch.global.L2 [%0];" :: "l"(p))

// ---------------- device scratch (static, no allocs) ----------------
__device__ float g_S[NS * D];        // state + fast
__device__ float g_Keq[NS * D];      // keys @ Wr
__device__ float g_cq[NS];           // keys @ br
__device__ float g_sWc[NS];          // S @ Wc[0, D:2D]
__device__ float g_M1[NS * D];       // attn.T @ (h + nm)
__device__ float g_G[NS * NS];       // attn.T @ attn
__device__ float g_asum[NS];         // sum_b attn
__device__ float g_sadd;             // sum_b sigmoid(ctrl0)
__device__ float g_delta[NS * D];    // partial delta

// ---------------- prep1: S = state + fast ; zero accumulators ----------------
__global__ void k_prep1(const float* __restrict__ state, const float* __restrict__ fast) {
    int i = blockIdx.x * blockDim.x + threadIdx.x;   // 0..16383
    g_S[i]     = state[i] + fast[i];
    g_Keq[i]   = 0.f;
    g_M1[i]    = 0.f;
    g_delta[i] = 0.f;
    if (i < NS * NS) g_G[i] = 0.f;
    if (i < NS)      g_asum[i] = 0.f;
    if (i == 0)      g_sadd = 0.f;
}

// ---------------- keq: Keq[s,i] = sum_j keys[s,j] * Wr[j,i] ----------------
__global__ void k_keq(const float* __restrict__ keys, const float* __restrict__ Wr) {
    __shared__ float ks[NS][128];
    int t = threadIdx.x;
    int j0 = blockIdx.y * 128;
    int i  = blockIdx.x * 256 + t;
    for (int idx = t; idx < NS * 128; idx += 256)
        ks[idx >> 7][idx & 127] = keys[(idx >> 7) * D + j0 + (idx & 127)];
    __syncthreads();
    float acc[NS];
#pragma unroll
    for (int s = 0; s < NS; s++) acc[s] = 0.f;
    for (int jj = 0; jj < 128; jj++) {
        float w = Wr[(size_t)(j0 + jj) * D + i];
#pragma unroll
        for (int s = 0; s < NS; s++) acc[s] += ks[s][jj] * w;
    }
#pragma unroll
    for (int s = 0; s < NS; s++) atomicAdd(&g_Keq[s * D + i], acc[s]);
}

// ---------------- prep2: cq[s] = keys[s].br ; sWc[s] = S[s].Wc[0,D:] ----------------
__global__ void k_prep2(const float* __restrict__ keys, const float* __restrict__ br,
                        const float* __restrict__ Wc) {
    __shared__ float rbuf[8];
    int s = blockIdx.x >> 1;
    int which = blockIdx.x & 1;
    const float* a = which ? (g_S + s * D) : (keys + s * D);
    const float* w = which ? (Wc + D) : br;
    float acc = 0.f;
    for (int i = threadIdx.x; i < D; i += 256) acc += a[i] * w[i];
#pragma unroll
    for (int off = 16; off; off >>= 1) acc += __shfl_xor_sync(0xffffffffu, acc, off);
    if ((threadIdx.x & 31) == 0) rbuf[threadIdx.x >> 5] = acc;
    __syncthreads();
    if (threadIdx.x == 0) {
        float tot = 0.f;
#pragma unroll
        for (int k = 0; k < 8; k++) tot += rbuf[k];
        if (which) g_sWc[s] = tot; else g_cq[s] = tot;
    }
}

// ---------------- P1: 4 rows/warp, 8 lanes/row, MLP-8, intra-quad prefetch ---
__global__ __launch_bounds__(256)
void k_part(const float* __restrict__ h, const float* __restrict__ Wc,
            const float* __restrict__ bc, float* __restrict__ attn_out) {
    extern __shared__ float kq_sm[];    // [9][2048]
    __shared__ float cq_sm[8], swc_sm[8];
    int t = threadIdx.x;
    for (int i = t; i < (NS * D) / 4; i += 256)
        ((float4*)kq_sm)[i] = ((const float4*)g_Keq)[i];
    for (int i = t; i < D / 4; i += 256)
        ((float4*)(kq_sm + NS * D))[i] = ((const float4*)Wc)[i];
    if (t < 8) { cq_sm[t] = g_cq[t]; swc_sm[t] = g_sWc[t]; }
    float bc0 = bc[0];
    __syncthreads();

    int lane = t & 31;
    int sub  = lane >> 3;       // row within quad (0..3)
    int cid  = lane & 7;        // column chunk (0..7)
    int gw = blockIdx.x * 8 + (t >> 5);
    int nw = gridDim.x * 8;
    float saddl = 0.f;
    const char* kbase = (const char*)kq_sm + cid * 16;

    for (int q = gw; q < BSZ / 4; q += nw) {
        int row = q * 4 + sub;
        const char* hrow = (const char*)(h + (size_t)row * D);
        // intra-quad prefetch: lines 8..63 are demanded 1-8 blk-iterations
        // from now — overlap their DRAM latency with compute on lines 0..7.
        // lane cid covers lines {8+cid, 16+cid, ..., 56+cid} (8 lanes x 7 = 56)
#pragma unroll
        for (int p = 0; p < 7; p++)
            PREFETCH_L2(hrow + (size_t)(8 + cid + 8 * p) * 128);
        const char* hp = hrow + cid * 16;
        unsigned long long acc[9];
#pragma unroll
        for (int v = 0; v < 9; v++) acc[v] = 0ull;
#pragma unroll 1
        for (int blk = 0; blk < 64; blk += 8) {
            // 8 independent LDG.128 issued back-to-back (MLP 8)
            const char* hb = hp + (size_t)blk * 128;
            ulonglong2 hv0 = *(const ulonglong2*)(hb);
            ulonglong2 hv1 = *(const ulonglong2*)(hb + 128);
            ulonglong2 hv2 = *(const ulonglong2*)(hb + 256);
            ulonglong2 hv3 = *(const ulonglong2*)(hb + 384);
            ulonglong2 hv4 = *(const ulonglong2*)(hb + 512);
            ulonglong2 hv5 = *(const ulonglong2*)(hb + 640);
            ulonglong2 hv6 = *(const ulonglong2*)(hb + 768);
            ulonglong2 hv7 = *(const ulonglong2*)(hb + 896);
            const char* kb = kbase + blk * 128;
#pragma unroll
            for (int v = 0; v < 9; v++) {
                const char* kv = kb + v * (D * 4);
                ulonglong2 k0 = *(const ulonglong2*)(kv);
                FMA2(acc[v], hv0.x, k0.x); FMA2(acc[v], hv0.y, k0.y);
                ulonglong2 k1 = *(const ulonglong2*)(kv + 128);
                FMA2(acc[v], hv1.x, k1.x); FMA2(acc[v], hv1.y, k1.y);
                ulonglong2 k2 = *(const ulonglong2*)(kv + 256);
                FMA2(acc[v], hv2.x, k2.x); FMA2(acc[v], hv2.y, k2.y);
                ulonglong2 k3 = *(const ulonglong2*)(kv + 384);
                FMA2(acc[v], hv3.x, k3.x); FMA2(acc[v], hv3.y, k3.y);
                ulonglong2 k4 = *(const ulonglong2*)(kv + 512);
                FMA2(acc[v], hv4.x, k4.x); FMA2(acc[v], hv4.y, k4.y);
                ulonglong2 k5 = *(const ulonglong2*)(kv + 640);
                FMA2(acc[v], hv5.x, k5.x); FMA2(acc[v], hv5.y, k5.y);
                ulonglong2 k6 = *(const ulonglong2*)(kv + 768);
                FMA2(acc[v], hv6.x, k6.x); FMA2(acc[v], hv6.y, k6.y);
                ulonglong2 k7 = *(const ulonglong2*)(kv + 896);
                FMA2(acc[v], hv7.x, k7.x); FMA2(acc[v], hv7.y, k7.y);
            }
        }
        float r[9];
#pragma unroll
        for (int v = 0; v < 9; v++) {
            float lo, hi;
            UNPK(lo, hi, acc[v]);
            r[v] = lo + hi;
        }
        // butterfly over the 8 lanes of this row group
#pragma unroll
        for (int d = 1; d < 8; d <<= 1) {
#pragma unroll
            for (int v = 0; v < 9; v++)
                r[v] += __shfl_xor_sync(0xffffffffu, r[v], d);
        }
        // softmax (redundant across the 8 lanes)
        float lg[8], m = -1e30f;
#pragma unroll
        for (int v = 0; v < 8; v++) { lg[v] = r[v] + cq_sm[v]; m = fmaxf(m, lg[v]); }
        float se = 0.f;
#pragma unroll
        for (int v = 0; v < 8; v++) { lg[v] = expf(lg[v] - m); se += lg[v]; }
        float inv = 1.f / se;
        float aw = 0.f;
#pragma unroll
        for (int v = 0; v < 8; v++) { lg[v] *= inv; aw += lg[v] * swc_sm[v]; }
        if (cid == 0) {
            float4 o0 = {lg[0], lg[1], lg[2], lg[3]};
            float4 o1 = {lg[4], lg[5], lg[6], lg[7]};
            *(float4*)(attn_out + (size_t)row * NS)     = o0;
            *(float4*)(attn_out + (size_t)row * NS + 4) = o1;
            saddl += 1.f / (1.f + expf(-(r[8] + aw + bc0)));
        }
    }
    // sum saddl from lanes 0,8,16,24 (others hold 0)
    saddl += __shfl_xor_sync(0xffffffffu, saddl, 8);
    saddl += __shfl_xor_sync(0xffffffffu, saddl, 16);
    if (lane == 0) atomicAdd(&g_sadd, saddl);
}

// ---------------- P2: streaming, column-split, streaming cache hints ---------
#define SSTEP(s, as) { \
    float4 sv = s_sm[(s) * 256 + t]; \
    m1[s][0] += (as) * hn0; m1[s][1] += (as) * hn1; \
    m1[s][2] += (as) * hn2; m1[s][3] += (as) * hn3; \
    rd.x += (as) * sv.x; rd.y += (as) * sv.y; \
    rd.z += (as) * sv.z; rd.w += (as) * sv.w; }

__global__ __launch_bounds__(256)
void k_stream(const float* __restrict__ h, const float* __restrict__ nm,
              const float* __restrict__ attn, float* __restrict__ read_out) {
    extern __shared__ float4 s_sm[];   // [NS][256]: one 1024-col half of S
    int t = threadIdx.x;
    int half = blockIdx.x & 1;
    int colbase = half * (D / 2);
#pragma unroll
    for (int s = 0; s < NS; s++)
        s_sm[s * 256 + t] = ((const float4*)(g_S + s * D + colbase))[t];
    float m1[NS][4];
#pragma unroll
    for (int s = 0; s < NS; s++) { m1[s][0]=0.f; m1[s][1]=0.f; m1[s][2]=0.f; m1[s][3]=0.f; }
    float gl = 0.f, asl = 0.f;
    int gi = (t >> 3) & 7, gj = t & 7;
    __syncthreads();

    int bstride = gridDim.x >> 1;
    int b0 = blockIdx.x >> 1;
    float4 hv = __ldcs((const float4*)(h  + (size_t)b0 * D + colbase) + t);
    float4 nv = __ldcs((const float4*)(nm + (size_t)b0 * D + colbase) + t);
    float4 a0 = ((const float4*)(attn + (size_t)b0 * NS))[0];
    float4 a1 = ((const float4*)(attn + (size_t)b0 * NS))[1];

    for (int b = b0; b < BSZ; b += bstride) {
        float4 hc = hv, nc = nv, ac0 = a0, ac1 = a1;
        int bn = b + bstride;
        if (bn < BSZ) {   // register prefetch (1 row ahead, evict-first)
            hv = __ldcs((const float4*)(h  + (size_t)bn * D + colbase) + t);
            nv = __ldcs((const float4*)(nm + (size_t)bn * D + colbase) + t);
            a0 = ((const float4*)(attn + (size_t)bn * NS))[0];
            a1 = ((const float4*)(attn + (size_t)bn * NS))[1];
        }
        int b2 = b + 3 * bstride;
        if (b2 < BSZ) {   // L2 prefetch (3 rows ahead, zero reg cost)
            PREFETCH_L2((const char*)(h  + (size_t)b2 * D + colbase) + t * 16);
            PREFETCH_L2((const char*)(nm + (size_t)b2 * D + colbase) + t * 16);
        }
        float hn0 = hc.x + nc.x, hn1 = hc.y + nc.y;
        float hn2 = hc.z + nc.z, hn3 = hc.w + nc.w;
        float4 rd = {0.f,0.f,0.f,0.f};
        SSTEP(0, ac0.x) SSTEP(1, ac0.y) SSTEP(2, ac0.z) SSTEP(3, ac0.w)
        SSTEP(4, ac1.x) SSTEP(5, ac1.y) SSTEP(6, ac1.z) SSTEP(7, ac1.w)
        __stcs((float4*)(read_out + (size_t)b * D + colbase) + t, rd);
        if (half == 0 && t < 64) {   // G/asum: only warps 0-1 issue these loads
            gl  += attn[(size_t)b * NS + gi] * attn[(size_t)b * NS + gj];
            asl += attn[(size_t)b * NS + gj];
        }
    }
#pragma unroll
    for (int s = 0; s < NS; s++) {
#pragma unroll
        for (int k = 0; k < 4; k++)
            atomicAdd(&g_M1[s * D + colbase + 4 * t + k], m1[s][k]);
    }
    if (half == 0 && t < 64) atomicAdd(&g_G[t], gl);
    if (half == 0 && t < 8)  atomicAdd(&g_asum[t], asl);
}

// ---------------- delta partials: [M1 | G@S] @ Ww^T ----------------
__global__ __launch_bounds__(256)
void k_delta(const float* __restrict__ Ww) {
    __shared__ float u_sm[NS][256];
    __shared__ float gsm[64];
    int t = threadIdx.x;
    int i0 = blockIdx.y * 256;                  // 0..4095
    int ui0 = i0 & (D - 1);
    if (i0 >= D && t < 64) gsm[t] = g_G[t];
    __syncthreads();
    if (i0 < D) {
        for (int idx = t; idx < NS * 256; idx += 256)
            u_sm[idx >> 8][idx & 255] = g_M1[(idx >> 8) * D + ui0 + (idx & 255)];
    } else {
        float sv[NS];
#pragma unroll
        for (int sp = 0; sp < NS; sp++) sv[sp] = g_S[sp * D + ui0 + t];
#pragma unroll
        for (int s = 0; s < NS; s++) {
            float u = 0.f;
#pragma unroll
            for (int sp = 0; sp < NS; sp++) u += gsm[s * NS + sp] * sv[sp];
            u_sm[s][t] = u;
        }
    }
    __syncthreads();
    int o = blockIdx.x * 256 + t;
    float acc[NS];
#pragma unroll
    for (int s = 0; s < NS; s++) acc[s] = 0.f;
    const float* wrow = Ww + (size_t)o * TWOD + i0;
    for (int ii = 0; ii < 256; ii += 4) {
        float4 w = *(const float4*)(wrow + ii);
#pragma unroll
        for (int s = 0; s < NS; s++)
            acc[s] += u_sm[s][ii]*w.x + u_sm[s][ii+1]*w.y + u_sm[s][ii+2]*w.z + u_sm[s][ii+3]*w.w;
    }
#pragma unroll
    for (int s = 0; s < NS; s++) atomicAdd(&g_delta[s * D + o], acc[s]);
}

// ---------------- final: alpha, new_state, new_fast ----------------
__global__ void k_final(const float* __restrict__ bw, const float* __restrict__ state,
                        const float* __restrict__ fast, float* __restrict__ out) {
    int idx = blockIdx.x * 256 + threadIdx.x;   // 16384
    float mean = g_sadd * (1.f / (float)BSZ);
    float alpha = 0.02f + 0.98f * mean;
    alpha = fminf(fmaxf(alpha, 0.f), 1.f);      // ALPHA_BOOST = 1
    int s = idx >> 11, o = idx & (D - 1);
    float delta = g_delta[idx] + g_asum[s] * bw[o];
    out[OFF_NS + idx] = (1.f - alpha) * state[idx] + alpha * delta;
    out[OFF_NF + idx] = 0.95f * fast[idx] + 0.05f * delta;
    if (idx == 0) out[OFF_ALPHA] = alpha;
}

// ---------------- launch ----------------
extern "C" void kernel_launch(void* const* d_in, const int* in_sizes, int n_in,
                              void* d_out, int out_size) {
    const float* h     = (const float*)d_in[0];
    const float* nm    = (const float*)d_in[1];
    const float* keys  = (const float*)d_in[2];
    const float* Wr    = (const float*)d_in[3];
    const float* br    = (const float*)d_in[4];
    const float* Wc    = (const float*)d_in[5];
    const float* bc    = (const float*)d_in[6];
    const float* Ww    = (const float*)d_in[7];
    const float* bw    = (const float*)d_in[8];
    const float* state = (const float*)d_in[9];
    const float* fast  = (const float*)d_in[10];
    float* out = (float*)d_out;

    const int SMEM_PART = 9 * D * sizeof(float);          // 72KB keq tile
    const int SMEM_STRM = NS * 256 * sizeof(float4);      // 32KB S half tile
    cudaFuncSetAttribute(k_part,   cudaFuncAttributeMaxDynamicSharedMemorySize, SMEM_PART);
    cudaFuncSetAttribute(k_stream, cudaFuncAttributeMaxDynamicSharedMemorySize, SMEM_STRM);

    k_prep1<<<64, 256>>>(state, fast);
    k_keq<<<dim3(8, 16), 256>>>(keys, Wr);
    k_prep2<<<16, 256>>>(keys, br, Wc);
    k_part<<<512, 256, SMEM_PART>>>(h, Wc, bc, out + OFF_ATTN);   // 4096 warps x 1 quad
    k_stream<<<888, 256, SMEM_STRM>>>(h, nm, out + OFF_ATTN, out + OFF_READ);
    k_delta<<<dim3(8, 16), 256>>>(Ww);
    k_final<<<64, 256>>>(bw, state, fast, out);
}

// round 16
// speedup vs baseline: 1.3390x; 1.0076x over previous
#include <cuda_runtime.h>
#include <math.h>

#define D      2048
#define NS     8
#define BSZ    16384
#define TWOD   (2*D)

// output layout: read [B,D] | attn [B,8] | alpha [1] | new_state [8,D] | new_fast [8,D]
#define OFF_READ   0
#define OFF_ATTN   ((size_t)BSZ * D)
#define OFF_ALPHA  (OFF_ATTN + (size_t)BSZ * NS)
#define OFF_NS     (OFF_ALPHA + 1)
#define OFF_NF     (OFF_NS + (size_t)NS * D)

#define FMA2(acc, a, b) \
    asm("fma.rn.f32x2 %0, %1, %2, %0;" : "+l"(acc) : "l"(a), "l"(b))
#define UNPK(lo, hi, v) \
    asm("mov.b64 {%0, %1}, %2;" : "=f"(lo), "=f"(hi) : "l"(v))
#define PREFETCH_L2(p) \
    asm volatile("prefetch.global.L2 [%0];" :: "l"(p))

// ---------------- device scratch (static, no allocs) ----------------
__device__ float g_S[NS * D];        // state + fast
__device__ float g_Keq[NS * D];      // keys @ Wr
__device__ float g_cq[NS];           // keys @ br
__device__ float g_sWc[NS];          // S @ Wc[0, D:2D]
__device__ float g_M1[NS * D];       // attn.T @ (h + nm)
__device__ float g_G[NS * NS];       // attn.T @ attn
__device__ float g_asum[NS];         // sum_b attn
__device__ float g_sadd;             // sum_b sigmoid(ctrl0)
__device__ float g_delta[NS * D];    // partial delta

// ---------------- merged prep: prep1 | prep2 | keq in one launch -------------
// blocks 0-63: S = state+fast, zero accumulators
// blocks 64-79: cq[s] = keys[s].br ; sWc[s] = (state+fast)[s].Wc[0,D:]
// blocks 80-207: Keq accumulation (16 j-chunks x 8 i-chunks)
__global__ __launch_bounds__(256)
void k_prep(const float* __restrict__ state, const float* __restrict__ fast,
            const float* __restrict__ keys, const float* __restrict__ br,
            const float* __restrict__ Wc, const float* __restrict__ Wr) {
    int t = threadIdx.x;
    int bid = blockIdx.x;
    if (bid < 64) {
        int i = bid * 256 + t;   // 0..16383
        g_S[i]     = state[i] + fast[i];
        g_Keq[i]   = 0.f;
        g_M1[i]    = 0.f;
        g_delta[i] = 0.f;
        if (i < NS * NS) g_G[i] = 0.f;
        if (i < NS)      g_asum[i] = 0.f;
        if (i == 0)      g_sadd = 0.f;
        return;
    }
    if (bid < 80) {
        __shared__ float rbuf[8];
        int s = (bid - 64) >> 1;
        int which = (bid - 64) & 1;
        float acc = 0.f;
        if (which) {
            for (int i = t; i < D; i += 256)
                acc += (state[s * D + i] + fast[s * D + i]) * Wc[D + i];
        } else {
            for (int i = t; i < D; i += 256)
                acc += keys[s * D + i] * br[i];
        }
#pragma unroll
        for (int off = 16; off; off >>= 1) acc += __shfl_xor_sync(0xffffffffu, acc, off);
        if ((t & 31) == 0) rbuf[t >> 5] = acc;
        __syncthreads();
        if (t == 0) {
            float tot = 0.f;
#pragma unroll
            for (int k = 0; k < 8; k++) tot += rbuf[k];
            if (which) g_sWc[s] = tot; else g_cq[s] = tot;
        }
        return;
    }
    // keq blocks
    __shared__ float ks[NS][128];
    int kb = bid - 80;                 // 0..127
    int j0 = (kb & 15) * 128;
    int i  = (kb >> 4) * 256 + t;
    for (int idx = t; idx < NS * 128; idx += 256)
        ks[idx >> 7][idx & 127] = keys[(idx >> 7) * D + j0 + (idx & 127)];
    __syncthreads();
    float acc[NS];
#pragma unroll
    for (int s = 0; s < NS; s++) acc[s] = 0.f;
    for (int jj = 0; jj < 128; jj++) {
        float w = Wr[(size_t)(j0 + jj) * D + i];
#pragma unroll
        for (int s = 0; s < NS; s++) acc[s] += ks[s][jj] * w;
    }
#pragma unroll
    for (int s = 0; s < NS; s++) atomicAdd(&g_Keq[s * D + i], acc[s]);
}

// ---------------- P1: 4 rows/warp, 8 lanes/row, MLP-8, intra-quad prefetch ---
__global__ __launch_bounds__(256)
void k_part(const float* __restrict__ h, const float* __restrict__ Wc,
            const float* __restrict__ bc, float* __restrict__ attn_out) {
    extern __shared__ float kq_sm[];    // [9][2048]
    __shared__ float cq_sm[8], swc_sm[8];
    int t = threadIdx.x;
    for (int i = t; i < (NS * D) / 4; i += 256)
        ((float4*)kq_sm)[i] = ((const float4*)g_Keq)[i];
    for (int i = t; i < D / 4; i += 256)
        ((float4*)(kq_sm + NS * D))[i] = ((const float4*)Wc)[i];
    if (t < 8) { cq_sm[t] = g_cq[t]; swc_sm[t] = g_sWc[t]; }
    float bc0 = bc[0];
    __syncthreads();

    int lane = t & 31;
    int sub  = lane >> 3;       // row within quad (0..3)
    int cid  = lane & 7;        // column chunk (0..7)
    int gw = blockIdx.x * 8 + (t >> 5);
    int nw = gridDim.x * 8;
    float saddl = 0.f;
    const char* kbase = (const char*)kq_sm + cid * 16;

    for (int q = gw; q < BSZ / 4; q += nw) {
        int row = q * 4 + sub;
        const char* hrow = (const char*)(h + (size_t)row * D);
        // intra-quad prefetch: lines 8..63 demanded 1-8 blk-iterations later
#pragma unroll
        for (int p = 0; p < 7; p++)
            PREFETCH_L2(hrow + (size_t)(8 + cid + 8 * p) * 128);
        const char* hp = hrow + cid * 16;
        unsigned long long acc[9];
#pragma unroll
        for (int v = 0; v < 9; v++) acc[v] = 0ull;
#pragma unroll 1
        for (int blk = 0; blk < 64; blk += 8) {
            // 8 independent LDG.128 issued back-to-back (MLP 8)
            const char* hb = hp + (size_t)blk * 128;
            ulonglong2 hv0 = *(const ulonglong2*)(hb);
            ulonglong2 hv1 = *(const ulonglong2*)(hb + 128);
            ulonglong2 hv2 = *(const ulonglong2*)(hb + 256);
            ulonglong2 hv3 = *(const ulonglong2*)(hb + 384);
            ulonglong2 hv4 = *(const ulonglong2*)(hb + 512);
            ulonglong2 hv5 = *(const ulonglong2*)(hb + 640);
            ulonglong2 hv6 = *(const ulonglong2*)(hb + 768);
            ulonglong2 hv7 = *(const ulonglong2*)(hb + 896);
            const char* kb = kbase + blk * 128;
#pragma unroll
            for (int v = 0; v < 9; v++) {
                const char* kv = kb + v * (D * 4);
                ulonglong2 k0 = *(const ulonglong2*)(kv);
                FMA2(acc[v], hv0.x, k0.x); FMA2(acc[v], hv0.y, k0.y);
                ulonglong2 k1 = *(const ulonglong2*)(kv + 128);
                FMA2(acc[v], hv1.x, k1.x); FMA2(acc[v], hv1.y, k1.y);
                ulonglong2 k2 = *(const ulonglong2*)(kv + 256);
                FMA2(acc[v], hv2.x, k2.x); FMA2(acc[v], hv2.y, k2.y);
                ulonglong2 k3 = *(const ulonglong2*)(kv + 384);
                FMA2(acc[v], hv3.x, k3.x); FMA2(acc[v], hv3.y, k3.y);
                ulonglong2 k4 = *(const ulonglong2*)(kv + 512);
                FMA2(acc[v], hv4.x, k4.x); FMA2(acc[v], hv4.y, k4.y);
                ulonglong2 k5 = *(const ulonglong2*)(kv + 640);
                FMA2(acc[v], hv5.x, k5.x); FMA2(acc[v], hv5.y, k5.y);
                ulonglong2 k6 = *(const ulonglong2*)(kv + 768);
                FMA2(acc[v], hv6.x, k6.x); FMA2(acc[v], hv6.y, k6.y);
                ulonglong2 k7 = *(const ulonglong2*)(kv + 896);
                FMA2(acc[v], hv7.x, k7.x); FMA2(acc[v], hv7.y, k7.y);
            }
        }
        float r[9];
#pragma unroll
        for (int v = 0; v < 9; v++) {
            float lo, hi;
            UNPK(lo, hi, acc[v]);
            r[v] = lo + hi;
        }
#pragma unroll
        for (int d = 1; d < 8; d <<= 1) {
#pragma unroll
            for (int v = 0; v < 9; v++)
                r[v] += __shfl_xor_sync(0xffffffffu, r[v], d);
        }
        float lg[8], m = -1e30f;
#pragma unroll
        for (int v = 0; v < 8; v++) { lg[v] = r[v] + cq_sm[v]; m = fmaxf(m, lg[v]); }
        float se = 0.f;
#pragma unroll
        for (int v = 0; v < 8; v++) { lg[v] = expf(lg[v] - m); se += lg[v]; }
        float inv = 1.f / se;
        float aw = 0.f;
#pragma unroll
        for (int v = 0; v < 8; v++) { lg[v] *= inv; aw += lg[v] * swc_sm[v]; }
        if (cid == 0) {
            float4 o0 = {lg[0], lg[1], lg[2], lg[3]};
            float4 o1 = {lg[4], lg[5], lg[6], lg[7]};
            *(float4*)(attn_out + (size_t)row * NS)     = o0;
            *(float4*)(attn_out + (size_t)row * NS + 4) = o1;
            saddl += 1.f / (1.f + expf(-(r[8] + aw + bc0)));
        }
    }
    saddl += __shfl_xor_sync(0xffffffffu, saddl, 8);
    saddl += __shfl_xor_sync(0xffffffffu, saddl, 16);
    if (lane == 0) atomicAdd(&g_sadd, saddl);
}

// ---------------- P2: streaming, QUARTER-column split (512 cols/block) -------
#define SSTEP2(s, as) { \
    float2 sv = s_sm[(s) * 256 + t]; \
    m1[s][0] += (as) * hn0; m1[s][1] += (as) * hn1; \
    rd.x += (as) * sv.x; rd.y += (as) * sv.y; }

__global__ __launch_bounds__(256)
void k_stream(const float* __restrict__ h, const float* __restrict__ nm,
              const float* __restrict__ attn, float* __restrict__ read_out) {
    __shared__ float2 s_sm[NS * 256];  // one 512-col quarter of S (16KB)
    int t = threadIdx.x;
    int quarter = blockIdx.x & 3;
    int colbase = quarter * (D / 4);
#pragma unroll
    for (int s = 0; s < NS; s++)
        s_sm[s * 256 + t] = ((const float2*)(g_S + s * D + colbase))[t];
    float m1[NS][2];
#pragma unroll
    for (int s = 0; s < NS; s++) { m1[s][0] = 0.f; m1[s][1] = 0.f; }
    float gl = 0.f, asl = 0.f;
    int gi = (t >> 3) & 7, gj = t & 7;
    __syncthreads();

    int bstride = gridDim.x >> 2;   // 444 row-groups
    int b0 = blockIdx.x >> 2;
    float2 hv = __ldcs((const float2*)(h  + (size_t)b0 * D + colbase) + t);
    float2 nv = __ldcs((const float2*)(nm + (size_t)b0 * D + colbase) + t);
    float4 a0 = ((const float4*)(attn + (size_t)b0 * NS))[0];
    float4 a1 = ((const float4*)(attn + (size_t)b0 * NS))[1];

    for (int b = b0; b < BSZ; b += bstride) {
        float2 hc = hv, nc = nv;
        float4 ac0 = a0, ac1 = a1;
        int bn = b + bstride;
        if (bn < BSZ) {   // register prefetch (1 row ahead, evict-first)
            hv = __ldcs((const float2*)(h  + (size_t)bn * D + colbase) + t);
            nv = __ldcs((const float2*)(nm + (size_t)bn * D + colbase) + t);
            a0 = ((const float4*)(attn + (size_t)bn * NS))[0];
            a1 = ((const float4*)(attn + (size_t)bn * NS))[1];
        }
        int b2 = b + 3 * bstride;
        if (b2 < BSZ && (t & 15) == 0) {   // L2 prefetch, 1 per 128B line
            PREFETCH_L2((const char*)(h  + (size_t)b2 * D + colbase) + t * 8);
            PREFETCH_L2((const char*)(nm + (size_t)b2 * D + colbase) + t * 8);
        }
        float hn0 = hc.x + nc.x, hn1 = hc.y + nc.y;
        float2 rd = {0.f, 0.f};
        SSTEP2(0, ac0.x) SSTEP2(1, ac0.y) SSTEP2(2, ac0.z) SSTEP2(3, ac0.w)
        SSTEP2(4, ac1.x) SSTEP2(5, ac1.y) SSTEP2(6, ac1.z) SSTEP2(7, ac1.w)
        __stcs((float2*)(read_out + (size_t)b * D + colbase) + t, rd);
        if (quarter == 0 && t < 64) {   // G/asum: warps 0-1 of quarter 0 only
            gl  += attn[(size_t)b * NS + gi] * attn[(size_t)b * NS + gj];
            asl += attn[(size_t)b * NS + gj];
        }
    }
#pragma unroll
    for (int s = 0; s < NS; s++) {
        atomicAdd(&g_M1[s * D + colbase + 2 * t],     m1[s][0]);
        atomicAdd(&g_M1[s * D + colbase + 2 * t + 1], m1[s][1]);
    }
    if (quarter == 0 && t < 64) atomicAdd(&g_G[t], gl);
    if (quarter == 0 && t < 8)  atomicAdd(&g_asum[t], asl);
}

// ---------------- delta partials: [M1 | G@S] @ Ww^T ----------------
__global__ __launch_bounds__(256)
void k_delta(const float* __restrict__ Ww) {
    __shared__ float u_sm[NS][256];
    __shared__ float gsm[64];
    int t = threadIdx.x;
    int i0 = blockIdx.y * 256;                  // 0..4095
    int ui0 = i0 & (D - 1);
    if (i0 >= D && t < 64) gsm[t] = g_G[t];
    __syncthreads();
    if (i0 < D) {
        for (int idx = t; idx < NS * 256; idx += 256)
            u_sm[idx >> 8][idx & 255] = g_M1[(idx >> 8) * D + ui0 + (idx & 255)];
    } else {
        float sv[NS];
#pragma unroll
        for (int sp = 0; sp < NS; sp++) sv[sp] = g_S[sp * D + ui0 + t];
#pragma unroll
        for (int s = 0; s < NS; s++) {
            float u = 0.f;
#pragma unroll
            for (int sp = 0; sp < NS; sp++) u += gsm[s * NS + sp] * sv[sp];
            u_sm[s][t] = u;
        }
    }
    __syncthreads();
    int o = blockIdx.x * 256 + t;
    float acc[NS];
#pragma unroll
    for (int s = 0; s < NS; s++) acc[s] = 0.f;
    const float* wrow = Ww + (size_t)o * TWOD + i0;
    for (int ii = 0; ii < 256; ii += 4) {
        float4 w = *(const float4*)(wrow + ii);
#pragma unroll
        for (int s = 0; s < NS; s++)
            acc[s] += u_sm[s][ii]*w.x + u_sm[s][ii+1]*w.y + u_sm[s][ii+2]*w.z + u_sm[s][ii+3]*w.w;
    }
#pragma unroll
    for (int s = 0; s < NS; s++) atomicAdd(&g_delta[s * D + o], acc[s]);
}

// ---------------- final: alpha, new_state, new_fast ----------------
__global__ void k_final(const float* __restrict__ bw, const float* __restrict__ state,
                        const float* __restrict__ fast, float* __restrict__ out) {
    int idx = blockIdx.x * 256 + threadIdx.x;   // 16384
    float mean = g_sadd * (1.f / (float)BSZ);
    float alpha = 0.02f + 0.98f * mean;
    alpha = fminf(fmaxf(alpha, 0.f), 1.f);      // ALPHA_BOOST = 1
    int s = idx >> 11, o = idx & (D - 1);
    float delta = g_delta[idx] + g_asum[s] * bw[o];
    out[OFF_NS + idx] = (1.f - alpha) * state[idx] + alpha * delta;
    out[OFF_NF + idx] = 0.95f * fast[idx] + 0.05f * delta;
    if (idx == 0) out[OFF_ALPHA] = alpha;
}

// ---------------- launch ----------------
extern "C" void kernel_launch(void* const* d_in, const int* in_sizes, int n_in,
                              void* d_out, int out_size) {
    const float* h     = (const float*)d_in[0];
    const float* nm    = (const float*)d_in[1];
    const float* keys  = (const float*)d_in[2];
    const float* Wr    = (const float*)d_in[3];
    const float* br    = (const float*)d_in[4];
    const float* Wc    = (const float*)d_in[5];
    const float* bc    = (const float*)d_in[6];
    const float* Ww    = (const float*)d_in[7];
    const float* bw    = (const float*)d_in[8];
    const float* state = (const float*)d_in[9];
    const float* fast  = (const float*)d_in[10];
    float* out = (float*)d_out;

    const int SMEM_PART = 9 * D * sizeof(float);          // 72KB keq tile
    cudaFuncSetAttribute(k_part, cudaFuncAttributeMaxDynamicSharedMemorySize, SMEM_PART);

    k_prep<<<208, 256>>>(state, fast, keys, br, Wc, Wr);
    k_part<<<512, 256, SMEM_PART>>>(h, Wc, bc, out + OFF_ATTN);   // 4096 warps x 1 quad
    k_stream<<<1776, 256>>>(h, nm, out + OFF_ATTN, out + OFF_READ);
    k_delta<<<dim3(8, 16), 256>>>(Ww);
    k_final<<<64, 256>>>(bw, state, fast, out);
}